// round 1
// baseline (speedup 1.0000x reference)
#include <cuda_runtime.h>
#include <cstdint>
#include <cstddef>

#define D_DIM 64
#define L_DIM 100
#define B_DIM 256
#define H_DIM 10000
#define HC    32                 // h-columns per block
#define PITCH 36                 // floats per tile row (32 data + 4 pad)
#define TILE_FLOATS (L_DIM * PITCH)
#define NBUF  3

// per-(d,b): {lo*PITCH (bits), hi*PITCH (bits), alpha, 0}
__device__ float4 g_scratch[D_DIM * B_DIM];

__global__ void __launch_bounds__(256) precomp_kernel(const float* __restrict__ x) {
    int idx = blockIdx.x * 256 + threadIdx.x;
    if (idx >= D_DIM * B_DIM) return;
    int d = idx >> 8;
    int b = idx & 255;
    float xv = x[b * D_DIM + d];
    float xn = fminf(fmaxf(xv * (float)(L_DIM - 1), 0.0f), (float)(L_DIM - 1));
    float fl = floorf(xn);
    int lo = (int)fl;
    int hi = min(lo + 1, L_DIM - 1);
    float a = xn - fl;
    float4 r;
    r.x = __int_as_float(lo * PITCH);
    r.y = __int_as_float(hi * PITCH);
    r.z = a;
    r.w = 0.0f;
    g_scratch[idx] = r;
}

__device__ __forceinline__ void cp_async16(uint32_t smem, const void* gmem) {
    asm volatile("cp.async.cg.shared.global [%0], [%1], 16;\n" :: "r"(smem), "l"(gmem));
}
__device__ __forceinline__ void cp_commit() {
    asm volatile("cp.async.commit_group;\n" ::: "memory");
}
template <int N>
__device__ __forceinline__ void cp_wait() {
    asm volatile("cp.async.wait_group %0;\n" :: "n"(N) : "memory");
}

__global__ void __launch_bounds__(256, 2) encode_kernel(const float* __restrict__ base,
                                                        float* __restrict__ out) {
    __shared__ float tile[NBUF][TILE_FLOATS];

    const int tid = threadIdx.x;
    const int hg  = tid & 7;        // which float4 within the 32-column slice
    const int bg  = tid >> 3;       // batch group: 8 batches per thread
    const int h0  = blockIdx.x * HC;
    const int h   = h0 + hg * 4;
    const bool h_ok = (h < H_DIM);  // H % 4 == 0, so whole-vec4 validity

    // issue tile load for dim d into buffer buf: base[d, 0..99, h0..h0+31]
    auto load_tile = [&](int d, int buf) {
        const float* src = base + (size_t)d * (L_DIM * H_DIM) + h0;
        uint32_t sbase = (uint32_t)__cvta_generic_to_shared(&tile[buf][0]);
        for (int v = tid; v < L_DIM * 8; v += 256) {
            int row = v >> 3;
            int col = v & 7;
            int hh = h0 + col * 4;
            if (hh < H_DIM) {
                cp_async16(sbase + (uint32_t)(row * PITCH + col * 4) * 4,
                           src + (size_t)row * H_DIM + col * 4);
            }
        }
        cp_commit();
    };

    float acc[8][4];
#pragma unroll
    for (int i = 0; i < 8; ++i)
#pragma unroll
        for (int j = 0; j < 4; ++j) acc[i][j] = 0.0f;

    load_tile(0, 0);
    load_tile(1, 1);

    for (int d = 0; d < D_DIM; ++d) {
        if (d == D_DIM - 1) { cp_wait<0>(); } else { cp_wait<1>(); }
        __syncthreads();                        // tile(d) visible to all; tile(d-1) consumers done
        if (d + 2 < D_DIM) load_tile(d + 2, (d + 2) % NBUF);   // overwrites buf of tile(d-1)

        const float*  tb = tile[d % NBUF];
        const float4* sc = &g_scratch[d * B_DIM + bg * 8];
#pragma unroll
        for (int i = 0; i < 8; ++i) {
            float4 s = __ldg(&sc[i]);           // uniform across 8 lanes -> broadcast
            int off_lo = __float_as_int(s.x);
            int off_hi = __float_as_int(s.y);
            float a  = s.z;
            float w0 = 1.0f - a;
            float4 vl = *reinterpret_cast<const float4*>(tb + off_lo + hg * 4);
            float4 vh = *reinterpret_cast<const float4*>(tb + off_hi + hg * 4);
            acc[i][0] += w0 * vl.x + a * vh.x;
            acc[i][1] += w0 * vl.y + a * vh.y;
            acc[i][2] += w0 * vl.z + a * vh.z;
            acc[i][3] += w0 * vl.w + a * vh.w;
        }
    }

    if (h_ok) {
#pragma unroll
        for (int i = 0; i < 8; ++i) {
            float4 o;
            o.x = acc[i][0]; o.y = acc[i][1]; o.z = acc[i][2]; o.w = acc[i][3];
            *reinterpret_cast<float4*>(out + (size_t)(bg * 8 + i) * H_DIM + h) = o;
        }
    }
}

__global__ void __launch_bounds__(256) normalize_kernel(float* __restrict__ out) {
    int b = blockIdx.x;
    float* row = out + (size_t)b * H_DIM;

    float ss = 0.0f;
    for (int i = threadIdx.x * 4; i < H_DIM; i += 256 * 4) {
        float4 v = *reinterpret_cast<const float4*>(row + i);
        ss += v.x * v.x + v.y * v.y + v.z * v.z + v.w * v.w;
    }
#pragma unroll
    for (int o = 16; o; o >>= 1) ss += __shfl_down_sync(0xffffffffu, ss, o);

    __shared__ float red[8];
    __shared__ float inv_s;
    if ((threadIdx.x & 31) == 0) red[threadIdx.x >> 5] = ss;
    __syncthreads();
    if (threadIdx.x == 0) {
        float t = 0.0f;
#pragma unroll
        for (int i = 0; i < 8; ++i) t += red[i];
        inv_s = rsqrtf(t);
    }
    __syncthreads();
    float inv = inv_s;

    for (int i = threadIdx.x * 4; i < H_DIM; i += 256 * 4) {
        float4 v = *reinterpret_cast<const float4*>(row + i);
        v.x *= inv; v.y *= inv; v.z *= inv; v.w *= inv;
        *reinterpret_cast<float4*>(row + i) = v;
    }
}

extern "C" void kernel_launch(void* const* d_in, const int* in_sizes, int n_in,
                              void* d_out, int out_size) {
    // identify inputs by size, defensively
    const float* x;
    const float* base;
    if (in_sizes[0] == B_DIM * D_DIM) {
        x = (const float*)d_in[0];
        base = (const float*)d_in[1];
    } else {
        x = (const float*)d_in[1];
        base = (const float*)d_in[0];
    }
    float* out = (float*)d_out;

    precomp_kernel<<<(D_DIM * B_DIM + 255) / 256, 256>>>(x);

    int nblocks = (H_DIM + HC - 1) / HC;   // 313
    encode_kernel<<<nblocks, 256>>>(base, out);

    normalize_kernel<<<B_DIM, 256>>>(out);
}

// round 2
// speedup vs baseline: 1.6692x; 1.6692x over previous
#include <cuda_runtime.h>
#include <cstdint>
#include <cstddef>

#define D_DIM 64
#define L_DIM 100
#define B_DIM 256
#define H_DIM 10000
#define HC    32                 // h-columns per block
#define PITCH 36                 // floats per tile row (32 data + 4 pad)
#define TILE_FLOATS (L_DIM * PITCH)
#define NBUF  3
#define NTHR  512

// per-(d,b): {lo*PITCH (bits), hi*PITCH (bits), alpha, 0}
__device__ float4 g_scratch[D_DIM * B_DIM];

__global__ void __launch_bounds__(256) precomp_kernel(const float* __restrict__ x) {
    int idx = blockIdx.x * 256 + threadIdx.x;
    if (idx >= D_DIM * B_DIM) return;
    int d = idx >> 8;
    int b = idx & 255;
    float xv = x[b * D_DIM + d];
    float xn = fminf(fmaxf(xv * (float)(L_DIM - 1), 0.0f), (float)(L_DIM - 1));
    float fl = floorf(xn);
    int lo = (int)fl;
    int hi = min(lo + 1, L_DIM - 1);
    float a = xn - fl;
    float4 r;
    r.x = __int_as_float(lo * PITCH);
    r.y = __int_as_float(hi * PITCH);
    r.z = a;
    r.w = 0.0f;
    g_scratch[idx] = r;
}

__device__ __forceinline__ void cp_async16(uint32_t smem, const void* gmem) {
    asm volatile("cp.async.cg.shared.global [%0], [%1], 16;\n" :: "r"(smem), "l"(gmem));
}
__device__ __forceinline__ void cp_commit() {
    asm volatile("cp.async.commit_group;\n" ::: "memory");
}
template <int N>
__device__ __forceinline__ void cp_wait() {
    asm volatile("cp.async.wait_group %0;\n" :: "n"(N) : "memory");
}

// Blackwell packed fp32x2 helpers
__device__ __forceinline__ unsigned long long pk2(float lo, float hi) {
    unsigned long long r;
    asm("mov.b64 %0, {%1, %2};" : "=l"(r) : "f"(lo), "f"(hi));
    return r;
}
__device__ __forceinline__ unsigned long long ffma2(unsigned long long a,
                                                    unsigned long long b,
                                                    unsigned long long c) {
    unsigned long long d;
    asm("fma.rn.f32x2 %0, %1, %2, %3;" : "=l"(d) : "l"(a), "l"(b), "l"(c));
    return d;
}

__global__ void __launch_bounds__(NTHR, 2) encode_kernel(const float* __restrict__ base,
                                                         float* __restrict__ out) {
    __shared__ float  tile[NBUF][TILE_FLOATS];
    __shared__ float4 sscr[NBUF][B_DIM];

    const int tid = threadIdx.x;
    const int hg  = tid & 7;        // which float4 within the 32-column slice
    const int bg4 = tid >> 3;       // batch group: 4 batches per thread (0..63)
    const int h0  = blockIdx.x * HC;
    const int h   = h0 + hg * 4;
    const bool h_ok = (h < H_DIM);

    // stage base[d, 0..99, h0..h0+31] AND scratch[d, :] into buffer buf
    auto load_stage = [&](int d, int buf) {
        const float* src = base + (size_t)d * (L_DIM * H_DIM) + h0;
        uint32_t sbase = (uint32_t)__cvta_generic_to_shared(&tile[buf][0]);
        for (int v = tid; v < L_DIM * 8; v += NTHR) {
            int row = v >> 3;
            int col = v & 7;
            int hh = h0 + col * 4;
            if (hh < H_DIM) {
                cp_async16(sbase + (uint32_t)(row * PITCH + col * 4) * 4,
                           src + (size_t)row * H_DIM + col * 4);
            }
        }
        if (tid < B_DIM) {
            uint32_t sdst = (uint32_t)__cvta_generic_to_shared(&sscr[buf][tid]);
            cp_async16(sdst, &g_scratch[d * B_DIM + tid]);
        }
        cp_commit();
    };

    unsigned long long acc[4][2];
#pragma unroll
    for (int i = 0; i < 4; ++i) { acc[i][0] = 0ull; acc[i][1] = 0ull; }

    load_stage(0, 0);
    load_stage(1, 1);

    for (int d = 0; d < D_DIM; ++d) {
        if (d == D_DIM - 1) { cp_wait<0>(); } else { cp_wait<1>(); }
        __syncthreads();                          // tile(d)+scr(d) visible; d-1 consumers done
        if (d + 2 < D_DIM) load_stage(d + 2, (d + 2) % NBUF);

        const float*  tb = tile[d % NBUF];
        const float4* sc = &sscr[d % NBUF][bg4 * 4];
#pragma unroll
        for (int i = 0; i < 4; ++i) {
            float4 s = sc[i];                     // LDS.128 broadcast within 8-lane group
            int off_lo = __float_as_int(s.x);
            int off_hi = __float_as_int(s.y);
            float a  = s.z;
            unsigned long long wa = pk2(a, a);
            unsigned long long w0 = pk2(1.0f - a, 1.0f - a);
            ulonglong2 vl = *reinterpret_cast<const ulonglong2*>(tb + off_lo + hg * 4);
            ulonglong2 vh = *reinterpret_cast<const ulonglong2*>(tb + off_hi + hg * 4);
            acc[i][0] = ffma2(w0, vl.x, acc[i][0]);
            acc[i][1] = ffma2(w0, vl.y, acc[i][1]);
            acc[i][0] = ffma2(wa, vh.x, acc[i][0]);
            acc[i][1] = ffma2(wa, vh.y, acc[i][1]);
        }
    }

    if (h_ok) {
#pragma unroll
        for (int i = 0; i < 4; ++i) {
            ulonglong2 o;
            o.x = acc[i][0];
            o.y = acc[i][1];
            *reinterpret_cast<ulonglong2*>(out + (size_t)(bg4 * 4 + i) * H_DIM + h) = o;
        }
    }
}

__global__ void __launch_bounds__(256) normalize_kernel(float* __restrict__ out) {
    int b = blockIdx.x;
    float* row = out + (size_t)b * H_DIM;

    float ss = 0.0f;
    for (int i = threadIdx.x * 4; i < H_DIM; i += 256 * 4) {
        float4 v = *reinterpret_cast<const float4*>(row + i);
        ss += v.x * v.x + v.y * v.y + v.z * v.z + v.w * v.w;
    }
#pragma unroll
    for (int o = 16; o; o >>= 1) ss += __shfl_down_sync(0xffffffffu, ss, o);

    __shared__ float red[8];
    __shared__ float inv_s;
    if ((threadIdx.x & 31) == 0) red[threadIdx.x >> 5] = ss;
    __syncthreads();
    if (threadIdx.x == 0) {
        float t = 0.0f;
#pragma unroll
        for (int i = 0; i < 8; ++i) t += red[i];
        inv_s = rsqrtf(t);
    }
    __syncthreads();
    float inv = inv_s;

    for (int i = threadIdx.x * 4; i < H_DIM; i += 256 * 4) {
        float4 v = *reinterpret_cast<const float4*>(row + i);
        v.x *= inv; v.y *= inv; v.z *= inv; v.w *= inv;
        *reinterpret_cast<float4*>(row + i) = v;
    }
}

extern "C" void kernel_launch(void* const* d_in, const int* in_sizes, int n_in,
                              void* d_out, int out_size) {
    const float* x;
    const float* base;
    if (in_sizes[0] == B_DIM * D_DIM) {
        x = (const float*)d_in[0];
        base = (const float*)d_in[1];
    } else {
        x = (const float*)d_in[1];
        base = (const float*)d_in[0];
    }
    float* out = (float*)d_out;

    precomp_kernel<<<(D_DIM * B_DIM + 255) / 256, 256>>>(x);

    int nblocks = (H_DIM + HC - 1) / HC;   // 313
    encode_kernel<<<nblocks, NTHR>>>(base, out);

    normalize_kernel<<<B_DIM, 256>>>(out);
}